// round 17
// baseline (speedup 1.0000x reference)
#include <cuda_runtime.h>

// Problem constants (fixed by the reference: N=8192, K=10, M=3)
#define N_ROWS 8192
#define K_DIM  10
#define M_DIM  3

#define TILE_I 16
#define TILE_J 512
#define THREADS 128

// ---------------------------------------------------------------------------
// Fully fused single kernel.
//   mid[n][m] = max_k( |x[n][k]| + |w1[m][k]| )
//   out[i][j] = max_{m<3}( mid[i][m] + mid[j][m] )
//
// Block tile: 16 rows (i) x 512 cols (j), 128 threads, 8192 blocks (proven
// drain granularity). Each thread recomputes the mids for ITS OWN 4 j
// columns directly from x in registers (running-max over k: ~20 live regs,
// no shared staging, no bank conflicts) — the R14 lesson applied to fusion.
// 48 threads compute the 16x3 i-mids into a tiny shared array. This deletes
// the stage1 kernel + inter-kernel dependency (~1.8 us) for a small,
// latency-hidden per-block recompute.
// Store pattern unchanged: thread = 4 consecutive j, one STG.128 per row,
// 512B contiguous per warp.
// ---------------------------------------------------------------------------
__global__ __launch_bounds__(THREADS, 16)
void fused_kernel(const float* __restrict__ x,
                  const float* __restrict__ w1,
                  float* __restrict__ out) {
    __shared__ float sw[M_DIM * K_DIM];   // |w1|, 30 floats
    __shared__ float sa[M_DIM * TILE_I];  // i-tile mids, [m*16 + r]

    const int tid = threadIdx.x;
    const int j0 = blockIdx.x * TILE_J;
    const int i0 = blockIdx.y * TILE_I;

    if (tid < M_DIM * K_DIM) sw[tid] = fabsf(w1[tid]);
    __syncthreads();  // sw ready for all recompute below

    // ---- j-mids for this thread's 4 columns, in registers ----
    const int jg = j0 + tid * 4;          // global j (16B-aligned)
    float b0[4], b1[4], b2[4];            // b{m}[q]
#pragma unroll
    for (int q = 0; q < 4; ++q) {
        const float* xr = x + (long)(jg + q) * K_DIM;
        float v0 = -1e30f, v1 = -1e30f, v2 = -1e30f;
#pragma unroll
        for (int k = 0; k < K_DIM; ++k) {
            const float xv = fabsf(__ldg(&xr[k]));
            v0 = fmaxf(v0, xv + sw[0 * K_DIM + k]);
            v1 = fmaxf(v1, xv + sw[1 * K_DIM + k]);
            v2 = fmaxf(v2, xv + sw[2 * K_DIM + k]);
        }
        b0[q] = v0; b1[q] = v1; b2[q] = v2;
    }

    // ---- i-mids: 48 threads, one (m, r) each ----
    if (tid < M_DIM * TILE_I) {
        const int m = tid >> 4;           // tid / 16
        const int r = tid & 15;           // tid % 16
        const float* xr = x + (long)(i0 + r) * K_DIM;
        float v = -1e30f;
#pragma unroll
        for (int k = 0; k < K_DIM; ++k)
            v = fmaxf(v, fabsf(__ldg(&xr[k])) + sw[m * K_DIM + k]);
        sa[tid] = v;
    }
    __syncthreads();

    float4* out4 = reinterpret_cast<float4*>(out + (long)i0 * N_ROWS + jg);
    const long row_stride4 = N_ROWS / 4;  // in float4 units

#pragma unroll 4
    for (int r = 0; r < TILE_I; ++r) {
        const float a0 = sa[0 * TILE_I + r];
        const float a1 = sa[1 * TILE_I + r];
        const float a2 = sa[2 * TILE_I + r];

        float4 v;
        v.x = fmaxf(fmaxf(a0 + b0[0], a1 + b1[0]), a2 + b2[0]);
        v.y = fmaxf(fmaxf(a0 + b0[1], a1 + b1[1]), a2 + b2[1]);
        v.z = fmaxf(fmaxf(a0 + b0[2], a1 + b1[2]), a2 + b2[2]);
        v.w = fmaxf(fmaxf(a0 + b0[3], a1 + b1[3]), a2 + b2[3]);

        out4[(long)r * row_stride4] = v;
    }
}

// ---------------------------------------------------------------------------
extern "C" void kernel_launch(void* const* d_in, const int* in_sizes, int n_in,
                              void* d_out, int out_size) {
    const float* x  = (const float*)d_in[0];   // (8192, 10)
    const float* w1 = (const float*)d_in[1];   // (3, 10)
    float* out = (float*)d_out;                // (8192, 8192)

    dim3 grid(N_ROWS / TILE_J, N_ROWS / TILE_I);  // (16, 512) = 8192 blocks
    fused_kernel<<<grid, THREADS>>>(x, w1, out);
}